// round 10
// baseline (speedup 1.0000x reference)
#include <cuda_runtime.h>
#include <cuda_fp16.h>
#include <math.h>
#include <stdint.h>

#define B_ 8
#define N_ 2048
#define C_ 1024
#define H_ 16
#define D_ 64
#define R_ 5
#define RM_ 10

#define ATTN_ELEMS ((size_t)B_*N_*C_)              // 16777216
#define ESC_ELEMS  ((size_t)B_*H_*N_*R_)           // 1310720

// GEMM tiling: 256x128 CTA tile, 8 warps as 4x2 grid of 64x64 warp tiles
#define BM 256
#define BN 128
#define BK 32                 // K elems per stage
#define NSTAGE (C_/BK)        // 32
#define ROWP 40               // padded smem row stride in fp16 elems (80B)
#define A_TERM_BYTES (256*ROWP*2)        // 20480
#define B_TERM_BYTES (128*ROWP*2)        // 10240
#define STAGE_BYTES (2*A_TERM_BYTES + B_TERM_BYTES)   // 51200
#define NBUF 2
#define SMEM_DYN (NBUF*STAGE_BYTES)      // 102400

// combined scratch: one base pointer, uint32 element offsets
#define XN ((uint32_t)(B_*N_*C_))        // 16777216
#define WN ((uint32_t)(2*C_*C_))         // 2097152
#define OFF_XHI 0u
#define OFF_WHI XN
#define OFF_XLO (XN + WN)

__device__ __align__(256) __half g_hl[(size_t)(2u*XN + WN)];
__device__ float g_we[B_*H_*D_*R_];
__device__ float g_wr[B_*H_*D_*R_];
__device__ float g_S[H_*R_*R_*R_];

__constant__ int c_idx[RM_] = {0,227,454,682,909,1137,1364,1592,1819,2047};

// ---------------- PTX helpers (all baseline / portable) ----------------
__device__ __forceinline__ uint32_t smem_u32(const void* p){
    uint32_t a;
    asm("{ .reg .u64 t; cvta.to.shared.u64 t, %1; cvt.u32.u64 %0, t; }" : "=r"(a) : "l"(p));
    return a;
}
__device__ __forceinline__ void ldgsts16(uint32_t dst, const void* src){
    asm volatile("cp.async.cg.shared.global [%0], [%1], 16;" :: "r"(dst), "l"(src));
}
__device__ __forceinline__ void cp_commit(){ asm volatile("cp.async.commit_group;" ::: "memory"); }
__device__ __forceinline__ void cp_wait1(){ asm volatile("cp.async.wait_group 1;" ::: "memory"); }
__device__ __forceinline__ void cp_wait0(){ asm volatile("cp.async.wait_group 0;" ::: "memory"); }

__device__ __forceinline__ void ldm_x4(uint32_t* r, uint32_t addr){
    asm volatile("ldmatrix.sync.aligned.m8n8.x4.shared.b16 {%0,%1,%2,%3}, [%4];"
        : "=r"(r[0]),"=r"(r[1]),"=r"(r[2]),"=r"(r[3]) : "r"(addr));
}
__device__ __forceinline__ void mma_f16(float* d, const uint32_t* a, uint32_t b0, uint32_t b1){
    asm volatile("mma.sync.aligned.m16n8k16.row.col.f32.f16.f16.f32 "
        "{%0,%1,%2,%3}, {%4,%5,%6,%7}, {%8,%9}, {%0,%1,%2,%3};"
        : "+f"(d[0]),"+f"(d[1]),"+f"(d[2]),"+f"(d[3])
        : "r"(a[0]),"r"(a[1]),"r"(a[2]),"r"(a[3]), "r"(b0),"r"(b1));
}

// ---------------------------------------------------------------------------
// Convert fp32 -> fp16 hi/lo split for x, hi-only for qk_w
// ---------------------------------------------------------------------------
__global__ void k_convert(const float* __restrict__ x, const float* __restrict__ qk_w)
{
    const size_t nx4 = (size_t)XN/4;
    const size_t nw4 = (size_t)WN/4;
    const size_t tot = nx4 + nw4;
    size_t stride = (size_t)gridDim.x*blockDim.x;
    uint2* g4 = (uint2*)g_hl;
    for (size_t t = (size_t)blockIdx.x*blockDim.x + threadIdx.x; t < tot; t += stride){
        if (t < nx4){
            float4 v = ((const float4*)x)[t];
            __half h0 = __float2half_rn(v.x);
            __half h1 = __float2half_rn(v.y);
            __half h2 = __float2half_rn(v.z);
            __half h3 = __float2half_rn(v.w);
            __half l0 = __float2half_rn(v.x - __half2float(h0));
            __half l1 = __float2half_rn(v.y - __half2float(h1));
            __half l2 = __float2half_rn(v.z - __half2float(h2));
            __half l3 = __float2half_rn(v.w - __half2float(h3));
            uint2 hp, lp;
            hp.x = ((uint32_t)__half_as_ushort(h1) << 16) | __half_as_ushort(h0);
            hp.y = ((uint32_t)__half_as_ushort(h3) << 16) | __half_as_ushort(h2);
            lp.x = ((uint32_t)__half_as_ushort(l1) << 16) | __half_as_ushort(l0);
            lp.y = ((uint32_t)__half_as_ushort(l3) << 16) | __half_as_ushort(l2);
            g4[OFF_XHI/4 + t] = hp;
            g4[OFF_XLO/4 + t] = lp;
        } else {
            size_t w = t - nx4;
            float4 v = ((const float4*)qk_w)[w];
            uint2 hp;
            hp.x = ((uint32_t)__half_as_ushort(__float2half_rn(v.y)) << 16)
                 | __half_as_ushort(__float2half_rn(v.x));
            hp.y = ((uint32_t)__half_as_ushort(__float2half_rn(v.w)) << 16)
                 | __half_as_ushort(__float2half_rn(v.z));
            g4[OFF_WHI/4 + w] = hp;
        }
    }
}

// ---------------------------------------------------------------------------
// we/wr inducing-point projections (fp32, tiny)
// ---------------------------------------------------------------------------
__global__ void k_setup_wewr(const float* __restrict__ x,
                             const float* __restrict__ we_p,
                             const float* __restrict__ wr_p)
{
    int blk = blockIdx.x;
    int b = blk >> 4, h = blk & 15;
    int d = threadIdx.x;
    if (d >= D_) return;
    float xs[RM_];
#pragma unroll
    for (int m = 0; m < RM_; m++)
        xs[m] = x[((size_t)(b*N_ + c_idx[m]))*C_ + h*D_ + d];
#pragma unroll
    for (int a = 0; a < R_; a++){
        float se = 0.f, sr = 0.f;
#pragma unroll
        for (int m = 0; m < RM_; m++){
            se += xs[m] * we_p[(h*RM_ + m)*R_ + a];
            sr += xs[m] * wr_p[(h*RM_ + m)*R_ + a];
        }
        g_we[((b*H_ + h)*D_ + d)*R_ + a] = se;
        g_wr[((b*H_ + h)*D_ + d)*R_ + a] = sr;
    }
}

// ---------------------------------------------------------------------------
// S matrices + KL scalar
// ---------------------------------------------------------------------------
__global__ void k_setup_skl(const float* __restrict__ log_lam,
                            const float* __restrict__ m_u,
                            const float* __restrict__ s_tri,
                            const float* __restrict__ log_ssqrt,
                            float* __restrict__ kl_out)
{
    int t = threadIdx.x;
    for (int i = t; i < H_*R_*R_*R_; i += blockDim.x){
        int c = i % R_;
        int u = (i / R_) % R_;
        int a = (i / (R_*R_)) % R_;
        int h = i / (R_*R_*R_);
        float v = 0.f;
        if (u == c)      v = expf(log_ssqrt[(h*R_ + a)*R_ + u]);
        else if (u > c)  v = s_tri[((h*R_ + a)*R_ + u)*R_ + c];
        g_S[i] = v;
    }
    __shared__ float part[128];
    float p = 0.f;
    if (t < H_*R_){
        int h = t / R_, a = t % R_;
        float ll = log_lam[t];
        float e4 = expf(4.f*ll);
        float ss2 = 0.f;
        for (int u = 0; u < R_; u++){
            float dg = expf(log_ssqrt[(h*R_ + a)*R_ + u]);
            ss2 += dg*dg;
            for (int c = 0; c < u; c++){
                float v = s_tri[((h*R_ + a)*R_ + u)*R_ + c];
                ss2 += v*v;
            }
        }
        float mm = 0.f;
        for (int s = 0; s < R_; s++){
            float v = m_u[(h*R_ + a)*R_ + s];
            mm += v*v;
        }
        float lsum = 0.f;
        for (int u = 0; u < R_; u++) lsum += log_ssqrt[(h*R_ + a)*R_ + u];
        p = 0.5f*e4*(ss2 + mm) - lsum - 2.f*(float)R_*ll
            - (0.5f*(float)(R_*R_*H_)) / (float)(H_*R_);
    }
    part[t] = p;
    __syncthreads();
    if (t == 0){
        float s = 0.f;
        for (int i = 0; i < H_*R_; i++) s += part[i];
        *kl_out = s;
    }
}

// ---------------------------------------------------------------------------
// Fused main kernel: 256x128x1024 fp16-split (2-term) mma.sync GEMM
// 64x64 warp tiles (4x2 grid), occ 1, shuffle-reduced epilogue.
// ---------------------------------------------------------------------------
extern __shared__ char smem_raw[];

__global__ __launch_bounds__(256, 1)
void k_main(const float* __restrict__ mask,
            const float* __restrict__ eps,
            const float* __restrict__ log_lam,
            const float* __restrict__ m_u,
            const float* __restrict__ fw_w,
            const float* __restrict__ fw_b,
            float* __restrict__ out)
{
    const int nb = blockIdx.x, h = blockIdx.y, b = blockIdx.z;
    const int tid = threadIdx.x;
    const int wid = tid >> 5;
    const int lane = tid & 31;
    const uint32_t sb = smem_u32(smem_raw);

    __shared__ float we_s[D_*R_], wr_s[D_*R_], fww_s[D_*R_];
    __shared__ float S_s[R_*R_*R_], mu_s[R_*R_], lam2_s[R_], fwb_s[D_];

    {
        int base = (b*H_ + h)*D_*R_;
        for (int i = tid; i < D_*R_; i += 256){
            we_s[i] = g_we[base + i];
            wr_s[i] = g_wr[base + i];
            fww_s[i] = fw_w[i];
        }
        for (int i = tid; i < R_*R_*R_; i += 256) S_s[i] = g_S[h*R_*R_*R_ + i];
        for (int i = tid; i < R_*R_; i += 256)    mu_s[i] = m_u[h*R_*R_ + i];
        if (tid < R_)  lam2_s[tid] = expf(2.f*log_lam[h*R_ + tid]);
        if (tid < D_)  fwb_s[tid] = fw_b[tid];
    }

    const int rowA0 = b*N_ + nb*BM;

    // ---- cp.async load geometry: 10 chunks of 16B per thread per stage ----
    // c = i*256 + tid (0..2559): [0,1024) Ahi, [1024,2048) Alo, [2048,2560) Bhi
    uint32_t goff[10];
    uint32_t soff[10];
#pragma unroll
    for (int i = 0; i < 10; i++){
        int c = i*256 + tid;
        if (c < 2048){
            int term = c >> 10;               // 0=hi,1=lo
            int row  = (c >> 2) & 255;
            int quad = c & 3;
            soff[i] = term*A_TERM_BYTES + row*(ROWP*2) + quad*16;
            goff[i] = (term ? OFF_XLO : OFF_XHI) + (uint32_t)(rowA0 + row)*C_ + quad*8;
        } else {
            int cb = c - 2048;
            int row = cb >> 2;                // 0..127
            int quad = cb & 3;
            soff[i] = 2*A_TERM_BYTES + row*(ROWP*2) + quad*16;
            int wj = (row < 64) ? (h*64 + row) : (C_ + h*64 + (row - 64));
            goff[i] = OFF_WHI + (uint32_t)wj*C_ + quad*8;
        }
    }

    auto load_stage = [&](int kt, int buf){
        uint32_t stb = sb + buf*STAGE_BYTES;
        uint32_t ke = (uint32_t)kt*BK;
#pragma unroll
        for (int i = 0; i < 10; i++)
            ldgsts16(stb + soff[i], g_hl + (size_t)(goff[i] + ke));
        cp_commit();
    };

    // ---- warp tile geometry: 64x64 per warp, 4(m) x 2(n) grid ----
    const int wm = wid >> 1;        // 0..3 : m offset 64*wm
    const int wn = wid & 1;         // 0..1 : n offset 64*wn (0=q cols, 1=k cols)
    const int arow = lane & 15, acol8 = lane >> 4;

    uint32_t aoff[4], boff[4];
#pragma unroll
    for (int i = 0; i < 4; i++)
        aoff[i] = (wm*64 + i*16 + arow)*(ROWP*2) + acol8*16;
#pragma unroll
    for (int p = 0; p < 4; p++)
        boff[p] = (wn*64 + p*16 + arow)*(ROWP*2) + acol8*16;

    float acc[32][4];
#pragma unroll
    for (int i = 0; i < 32; i++)
#pragma unroll
        for (int j = 0; j < 4; j++) acc[i][j] = 0.f;

    // ---- pipeline: NBUF=2 double buffer ----
    load_stage(0, 0);
    __syncthreads();   // also covers shared-operand preload

    for (int kt = 0; kt < NSTAGE; kt++){
        const int cur = kt & 1;
        if (kt + 1 < NSTAGE){
            load_stage(kt + 1, cur ^ 1);
            cp_wait1();
        } else {
            cp_wait0();
        }
        __syncthreads();

        const uint32_t Ah = sb + cur*STAGE_BYTES;
        const uint32_t Al = Ah + A_TERM_BYTES;
        const uint32_t Bh = Ah + 2*A_TERM_BYTES;

#pragma unroll
        for (int kk = 0; kk < 2; kk++){
            const uint32_t kb = kk*32;
            uint32_t ah[4][4], bh[4][4];
#pragma unroll
            for (int i = 0; i < 4; i++) ldm_x4(ah[i], Ah + aoff[i] + kb);
#pragma unroll
            for (int p = 0; p < 4; p++) ldm_x4(bh[p], Bh + boff[p] + kb);
            // hh term: 32 independent HMMAs
#pragma unroll
            for (int i = 0; i < 4; i++)
#pragma unroll
                for (int j = 0; j < 8; j++){
                    int p = j >> 1, s = j & 1;
                    mma_f16(acc[i*8+j], ah[i], bh[p][s], bh[p][2+s]);
                }
            // lh term
            {
                uint32_t al[4][4];
#pragma unroll
                for (int i = 0; i < 4; i++) ldm_x4(al[i], Al + aoff[i] + kb);
#pragma unroll
                for (int i = 0; i < 4; i++)
#pragma unroll
                    for (int j = 0; j < 8; j++){
                        int p = j >> 1, s = j & 1;
                        mma_f16(acc[i*8+j], al[i], bh[p][s], bh[p][2+s]);
                    }
            }
        }
        __syncthreads();   // all reads of 'cur' done before next refill
    }

    // ---- shuffle epilogue: per-row {sumsq, 5 score dots} via lane reduction ----
    // lane holds: rows i*16 + (lane>>2) + 8*half, cols wn*64 + j*8 + 2*(lane&3) (+1)
    float* pq = (float*)smem_raw;            // [256][6] q-half partials
    float* pk = pq + 256*6;                  // [256][6] k-half partials
    {
        const float* tab = (wn == 0) ? we_s : wr_s;
        float* dst = (wn == 0) ? pq : pk;
        const int cbase = 2*(lane & 3);
#pragma unroll
        for (int i = 0; i < 4; i++){
#pragma unroll
            for (int half = 0; half < 2; half++){
                float p6[6] = {0,0,0,0,0,0};
#pragma unroll
                for (int j = 0; j < 8; j++){
                    float v0 = acc[i*8+j][half*2 + 0];
                    float v1 = acc[i*8+j][half*2 + 1];
                    int c0 = j*8 + cbase;
                    p6[0] += v0*v0 + v1*v1;
#pragma unroll
                    for (int a = 0; a < R_; a++)
                        p6[1+a] += v0*tab[c0*R_ + a] + v1*tab[(c0+1)*R_ + a];
                }
#pragma unroll
                for (int ofs = 1; ofs <= 2; ofs <<= 1)
#pragma unroll
                    for (int q = 0; q < 6; q++)
                        p6[q] += __shfl_xor_sync(0xFFFFFFFFu, p6[q], ofs);
                if ((lane & 3) == 0){
                    int rloc = wm*64 + i*16 + half*8 + (lane >> 2);
#pragma unroll
                    for (int q = 0; q < 6; q++) dst[rloc*6 + q] = p6[q];
                }
            }
        }
    }
    __syncthreads();

    // ---- final per-row epilogue: 256 threads, one row each ----
    {
        const int n = nb*BM + tid;
        const float mval = mask[b*N_ + n];
        const float sq = pq[tid*6], sk = pk[tid*6];
        float e[R_], rr[R_];
#pragma unroll
        for (int a = 0; a < R_; a++){ e[a] = pq[tid*6 + 1 + a]; rr[a] = pk[tid*6 + 1 + a]; }

        float sclq = mval / fmaxf(fabsf(mval)*sqrtf(sq), 1e-12f);
        float sclk = mval / fmaxf(fabsf(mval)*sqrtf(sk), 1e-12f);

        const size_t ebase = ((size_t)((b*H_ + h)*N_ + n))*R_;
        float es[R_], rs[R_], v1[R_];
#pragma unroll
        for (int a = 0; a < R_; a++){
            es[a] = e[a]*sclq;
            rs[a] = rr[a]*sclk;
            v1[a] = (es[a] + rs[a]) * lam2_s[a];
        }
        float* eo = out + ATTN_ELEMS + ebase;
        float* ro = out + ATTN_ELEMS + ESC_ELEMS + ebase;
#pragma unroll
        for (int a = 0; a < R_; a++){ eo[a] = es[a]; ro[a] = rs[a]; }

        float ev[R_];
#pragma unroll
        for (int u = 0; u < R_; u++) ev[u] = eps[ebase + u];
        float smp[R_];
#pragma unroll
        for (int s = 0; s < R_; s++){
            float am = 0.f;
#pragma unroll
            for (int a = 0; a < R_; a++) am += v1[a]*mu_s[a*R_ + s];
            smp[s] = am;
        }
#pragma unroll
        for (int a = 0; a < R_; a++)
#pragma unroll
            for (int u = 0; u < R_; u++){
                float f = v1[a]*ev[u];
#pragma unroll
                for (int c = 0; c < R_; c++)
                    smp[c] += f * S_s[(a*R_ + u)*R_ + c];
            }

        float* ob = out + ((size_t)(b*N_ + n))*C_ + h*D_;
#pragma unroll
        for (int d0 = 0; d0 < D_; d0 += 4){
            float4 o;
            float* op = (float*)&o;
#pragma unroll
            for (int dd = 0; dd < 4; dd++){
                float ao = fwb_s[d0 + dd];
#pragma unroll
                for (int a = 0; a < R_; a++) ao += smp[a]*fww_s[(d0 + dd)*R_ + a];
                op[dd] = ao;
            }
            *(float4*)(ob + d0) = o;
        }
    }
}

// ---------------------------------------------------------------------------
extern "C" void kernel_launch(void* const* d_in, const int* in_sizes, int n_in,
                              void* d_out, int out_size)
{
    const float* x         = (const float*)d_in[0];
    const float* mask      = (const float*)d_in[1];
    const float* eps       = (const float*)d_in[2];
    const float* qk_w      = (const float*)d_in[3];
    const float* we_p      = (const float*)d_in[4];
    const float* wr_p      = (const float*)d_in[5];
    const float* log_lam   = (const float*)d_in[6];
    const float* m_u       = (const float*)d_in[7];
    const float* s_tri     = (const float*)d_in[8];
    const float* log_ssqrt = (const float*)d_in[9];
    const float* fw_w      = (const float*)d_in[10];
    const float* fw_b      = (const float*)d_in[11];
    float* out = (float*)d_out;

    k_convert<<<4096, 256>>>(x, qk_w);
    k_setup_wewr<<<B_*H_, 64>>>(x, we_p, wr_p);
    k_setup_skl<<<1, 128>>>(log_lam, m_u, s_tri, log_ssqrt,
                            out + ATTN_ELEMS + 2*ESC_ELEMS);

    cudaFuncSetAttribute(k_main, cudaFuncAttributeMaxDynamicSharedMemorySize, SMEM_DYN);
    dim3 grid(N_/BM, H_, B_);
    k_main<<<grid, 256, SMEM_DYN>>>(mask, eps, log_lam, m_u, fw_w, fw_b, out);
}

// round 12
// speedup vs baseline: 1.0865x; 1.0865x over previous
#include <cuda_runtime.h>
#include <cuda_fp16.h>
#include <math.h>
#include <stdint.h>

#define B_ 8
#define N_ 2048
#define C_ 1024
#define H_ 16
#define D_ 64
#define R_ 5
#define RM_ 10

#define ATTN_ELEMS ((size_t)B_*N_*C_)              // 16777216
#define ESC_ELEMS  ((size_t)B_*H_*N_*R_)           // 1310720

// GEMM tiling
#define BM 128
#define BN 128
#define BK 32                 // K elems per stage
#define NSTAGE (C_/BK)        // 32
#define ROWP 40               // padded smem row stride in fp16 elems (80B)
#define TERM_BYTES (128*ROWP*2)          // one 128-row tile, 10240 B
#define STAGE_BYTES (3*TERM_BYTES)       // Ahi Alo Bhi = 30720 B
#define NBUF 3
#define CP 129
#define SMEM_DYN (NBUF*STAGE_BYTES)      // 92160 (>= C tile 128*129*4 = 66048)

// combined scratch: one base pointer, uint32 element offsets
#define XN ((uint32_t)(B_*N_*C_))        // 16777216
#define WN ((uint32_t)(2*C_*C_))         // 2097152
#define OFF_XHI 0u
#define OFF_WHI XN
#define OFF_XLO (XN + WN)

#define NB_CONV 4096

__device__ __align__(256) __half g_hl[(size_t)(2u*XN + WN)];
__device__ float g_we[B_*H_*D_*R_];
__device__ float g_wr[B_*H_*D_*R_];
__device__ float g_S[H_*R_*R_*R_];

__constant__ int c_idx[RM_] = {0,227,454,682,909,1137,1364,1592,1819,2047};

// ---------------- PTX helpers (all baseline / portable) ----------------
__device__ __forceinline__ uint32_t smem_u32(const void* p){
    uint32_t a;
    asm("{ .reg .u64 t; cvta.to.shared.u64 t, %1; cvt.u32.u64 %0, t; }" : "=r"(a) : "l"(p));
    return a;
}
__device__ __forceinline__ void ldgsts16(uint32_t dst, const void* src){
    asm volatile("cp.async.cg.shared.global [%0], [%1], 16;" :: "r"(dst), "l"(src));
}
__device__ __forceinline__ void cp_commit(){ asm volatile("cp.async.commit_group;" ::: "memory"); }
__device__ __forceinline__ void cp_wait1(){ asm volatile("cp.async.wait_group 1;" ::: "memory"); }
__device__ __forceinline__ void cp_wait0(){ asm volatile("cp.async.wait_group 0;" ::: "memory"); }

__device__ __forceinline__ void ldm_x4(uint32_t* r, uint32_t addr){
    asm volatile("ldmatrix.sync.aligned.m8n8.x4.shared.b16 {%0,%1,%2,%3}, [%4];"
        : "=r"(r[0]),"=r"(r[1]),"=r"(r[2]),"=r"(r[3]) : "r"(addr));
}
__device__ __forceinline__ void mma_f16(float* d, const uint32_t* a, uint32_t b0, uint32_t b1){
    asm volatile("mma.sync.aligned.m16n8k16.row.col.f32.f16.f16.f32 "
        "{%0,%1,%2,%3}, {%4,%5,%6,%7}, {%8,%9}, {%0,%1,%2,%3};"
        : "+f"(d[0]),"+f"(d[1]),"+f"(d[2]),"+f"(d[3])
        : "r"(a[0]),"r"(a[1]),"r"(a[2]),"r"(a[3]), "r"(b0),"r"(b1));
}

// ---------------------------------------------------------------------------
// Fused prep kernel:
//   blocks [0, NB_CONV):            fp32 -> fp16 hi/lo split (x), hi (qk_w)
//   blocks [NB_CONV, NB_CONV+128):  we/wr inducing-point projections
//   block  NB_CONV+128:             S matrices + KL scalar
// ---------------------------------------------------------------------------
__global__ void k_prep(const float* __restrict__ x, const float* __restrict__ qk_w,
                       const float* __restrict__ we_p, const float* __restrict__ wr_p,
                       const float* __restrict__ log_lam, const float* __restrict__ m_u,
                       const float* __restrict__ s_tri, const float* __restrict__ log_ssqrt,
                       float* __restrict__ kl_out)
{
    __shared__ float part[256];
    const int bid = blockIdx.x;

    if (bid < NB_CONV){
        const size_t nx4 = (size_t)XN/4;
        const size_t nw4 = (size_t)WN/4;
        const size_t tot = nx4 + nw4;
        const size_t stride = (size_t)NB_CONV*256;
        uint2* g4 = (uint2*)g_hl;
        for (size_t t = (size_t)bid*256 + threadIdx.x; t < tot; t += stride){
            if (t < nx4){
                float4 v = ((const float4*)x)[t];
                __half h0 = __float2half_rn(v.x);
                __half h1 = __float2half_rn(v.y);
                __half h2 = __float2half_rn(v.z);
                __half h3 = __float2half_rn(v.w);
                __half l0 = __float2half_rn(v.x - __half2float(h0));
                __half l1 = __float2half_rn(v.y - __half2float(h1));
                __half l2 = __float2half_rn(v.z - __half2float(h2));
                __half l3 = __float2half_rn(v.w - __half2float(h3));
                uint2 hp, lp;
                hp.x = ((uint32_t)__half_as_ushort(h1) << 16) | __half_as_ushort(h0);
                hp.y = ((uint32_t)__half_as_ushort(h3) << 16) | __half_as_ushort(h2);
                lp.x = ((uint32_t)__half_as_ushort(l1) << 16) | __half_as_ushort(l0);
                lp.y = ((uint32_t)__half_as_ushort(l3) << 16) | __half_as_ushort(l2);
                g4[OFF_XHI/4 + t] = hp;
                g4[OFF_XLO/4 + t] = lp;
            } else {
                size_t w = t - nx4;
                float4 v = ((const float4*)qk_w)[w];
                uint2 hp;
                hp.x = ((uint32_t)__half_as_ushort(__float2half_rn(v.y)) << 16)
                     | __half_as_ushort(__float2half_rn(v.x));
                hp.y = ((uint32_t)__half_as_ushort(__float2half_rn(v.w)) << 16)
                     | __half_as_ushort(__float2half_rn(v.z));
                g4[OFF_WHI/4 + w] = hp;
            }
        }
    } else if (bid < NB_CONV + 128){
        const int b2 = bid - NB_CONV;
        const int b = b2 >> 4, h = b2 & 15;
        const int d = threadIdx.x;
        if (d < D_){
            float xs[RM_];
#pragma unroll
            for (int m = 0; m < RM_; m++)
                xs[m] = x[((size_t)(b*N_ + c_idx[m]))*C_ + h*D_ + d];
#pragma unroll
            for (int a = 0; a < R_; a++){
                float se = 0.f, sr = 0.f;
#pragma unroll
                for (int m = 0; m < RM_; m++){
                    se += xs[m] * we_p[(h*RM_ + m)*R_ + a];
                    sr += xs[m] * wr_p[(h*RM_ + m)*R_ + a];
                }
                g_we[((b*H_ + h)*D_ + d)*R_ + a] = se;
                g_wr[((b*H_ + h)*D_ + d)*R_ + a] = sr;
            }
        }
    } else {
        const int t = threadIdx.x;
        for (int i = t; i < H_*R_*R_*R_; i += 256){
            int c = i % R_;
            int u = (i / R_) % R_;
            int a = (i / (R_*R_)) % R_;
            int h = i / (R_*R_*R_);
            float v = 0.f;
            if (u == c)      v = expf(log_ssqrt[(h*R_ + a)*R_ + u]);
            else if (u > c)  v = s_tri[((h*R_ + a)*R_ + u)*R_ + c];
            g_S[i] = v;
        }
        float p = 0.f;
        if (t < H_*R_){
            int h = t / R_, a = t % R_;
            float ll = log_lam[t];
            float e4 = expf(4.f*ll);
            float ss2 = 0.f;
            for (int u = 0; u < R_; u++){
                float dg = expf(log_ssqrt[(h*R_ + a)*R_ + u]);
                ss2 += dg*dg;
                for (int c = 0; c < u; c++){
                    float v = s_tri[((h*R_ + a)*R_ + u)*R_ + c];
                    ss2 += v*v;
                }
            }
            float mm = 0.f;
            for (int s = 0; s < R_; s++){
                float v = m_u[(h*R_ + a)*R_ + s];
                mm += v*v;
            }
            float lsum = 0.f;
            for (int u = 0; u < R_; u++) lsum += log_ssqrt[(h*R_ + a)*R_ + u];
            p = 0.5f*e4*(ss2 + mm) - lsum - 2.f*(float)R_*ll
                - (0.5f*(float)(R_*R_*H_)) / (float)(H_*R_);
        }
        part[t] = p;
        __syncthreads();
        if (t == 0){
            float s = 0.f;
            for (int i = 0; i < H_*R_; i++) s += part[i];
            *kl_out = s;
        }
    }
}

// ---------------------------------------------------------------------------
// Fused main kernel: 128x128x1024 fp16-split (2-term) mma.sync GEMM + epilogue
// NBUF=3 ring, lookahead 1, ONE barrier per stage, 2 CTAs/SM.
// ---------------------------------------------------------------------------
extern __shared__ char smem_raw[];

__global__ __launch_bounds__(256, 2)
void k_main(const float* __restrict__ mask,
            const float* __restrict__ eps,
            const float* __restrict__ log_lam,
            const float* __restrict__ m_u,
            const float* __restrict__ fw_w,
            const float* __restrict__ fw_b,
            float* __restrict__ out)
{
    const int nb = blockIdx.x, h = blockIdx.y, b = blockIdx.z;
    const int tid = threadIdx.x;
    const int wid = tid >> 5;
    const int lane = tid & 31;
    const uint32_t sb = smem_u32(smem_raw);

    __shared__ float we_s[D_*R_], wr_s[D_*R_], fww_s[D_*R_];
    __shared__ float S_s[R_*R_*R_], mu_s[R_*R_], lam2_s[R_], fwb_s[D_];

    {
        int base = (b*H_ + h)*D_*R_;
        for (int i = tid; i < D_*R_; i += 256){
            we_s[i] = g_we[base + i];
            wr_s[i] = g_wr[base + i];
            fww_s[i] = fw_w[i];
        }
        for (int i = tid; i < R_*R_*R_; i += 256) S_s[i] = g_S[h*R_*R_*R_ + i];
        for (int i = tid; i < R_*R_; i += 256)    mu_s[i] = m_u[h*R_*R_ + i];
        if (tid < R_)  lam2_s[tid] = expf(2.f*log_lam[h*R_ + tid]);
        if (tid < D_)  fwb_s[tid] = fw_b[tid];
    }

    const int rowA0 = b*N_ + nb*BM;

    // ---- cp.async load geometry: 6 chunks of 16B per thread per stage ----
    uint32_t goff[6];
    uint32_t soff[6];
#pragma unroll
    for (int i = 0; i < 6; i++){
        int c = i*256 + tid;
        int tile = c >> 9;
        int row  = (c >> 2) & 127;
        int quad = c & 3;
        soff[i] = tile*TERM_BYTES + row*(ROWP*2) + quad*16;
        if (tile == 0)
            goff[i] = OFF_XHI + (uint32_t)(rowA0 + row)*C_ + quad*8;
        else if (tile == 1)
            goff[i] = OFF_XLO + (uint32_t)(rowA0 + row)*C_ + quad*8;
        else {
            int wj = (row < 64) ? (h*64 + row) : (C_ + h*64 + (row - 64));
            goff[i] = OFF_WHI + (uint32_t)wj*C_ + quad*8;
        }
    }

    auto load_stage = [&](int kt, int buf){
        uint32_t stb = sb + buf*STAGE_BYTES;
        uint32_t ke = (uint32_t)kt*BK;
#pragma unroll
        for (int i = 0; i < 6; i++)
            ldgsts16(stb + soff[i], g_hl + (size_t)(goff[i] + ke));
        cp_commit();
    };

    // ---- warp tile geometry (64x32 per warp, 2x4 grid) ----
    const int wm = wid >> 2;
    const int wn = wid & 3;
    const int arow = lane & 15, acol8 = lane >> 4;

    uint32_t aoff[4], boff[2];
#pragma unroll
    for (int i = 0; i < 4; i++)
        aoff[i] = (wm*64 + i*16 + arow)*(ROWP*2) + acol8*16;
#pragma unroll
    for (int p = 0; p < 2; p++)
        boff[p] = (wn*32 + p*16 + arow)*(ROWP*2) + acol8*16;

    float acc[16][4];
#pragma unroll
    for (int i = 0; i < 16; i++)
#pragma unroll
        for (int j = 0; j < 4; j++) acc[i][j] = 0.f;

    // ---- pipeline: NBUF=3 ring, lookahead 1, single barrier per stage ----
    load_stage(0, 0);

    int buf_next = 1;      // (kt+1) % 3 tracker
    int buf_cur = 0;
    for (int kt = 0; kt < NSTAGE; kt++){
        if (kt + 1 < NSTAGE){
            load_stage(kt + 1, buf_next);
            cp_wait1();
        } else {
            cp_wait0();
        }
        __syncthreads();   // single barrier per stage (ring distance 2 mod 3)

        const uint32_t Ah = sb + buf_cur*STAGE_BYTES;
        const uint32_t Al = Ah + TERM_BYTES;
        const uint32_t Bh = Ah + 2*TERM_BYTES;

        buf_cur = buf_next;
        buf_next = (buf_next + 1 == NBUF) ? 0 : buf_next + 1;

#pragma unroll
        for (int kk = 0; kk < 2; kk++){
            const uint32_t kb = kk*32;
            uint32_t ah[4][4], bh[2][4];
#pragma unroll
            for (int i = 0; i < 4; i++) ldm_x4(ah[i], Ah + aoff[i] + kb);
#pragma unroll
            for (int p = 0; p < 2; p++) ldm_x4(bh[p], Bh + boff[p] + kb);
            // hh term
#pragma unroll
            for (int i = 0; i < 4; i++)
#pragma unroll
                for (int j = 0; j < 4; j++){
                    int p = j >> 1, s = j & 1;
                    mma_f16(acc[i*4+j], ah[i], bh[p][s], bh[p][2+s]);
                }
            // lh term
            {
                uint32_t al[4][4];
#pragma unroll
                for (int i = 0; i < 4; i++) ldm_x4(al[i], Al + aoff[i] + kb);
#pragma unroll
                for (int i = 0; i < 4; i++)
#pragma unroll
                    for (int j = 0; j < 4; j++){
                        int p = j >> 1, s = j & 1;
                        mma_f16(acc[i*4+j], al[i], bh[p][s], bh[p][2+s]);
                    }
            }
        }
    }
    __syncthreads();   // all MMAs/reads done before C-tile overwrite

    // ---- write C tile to smem (reuse stage buffers) ----
    float* Ct = (float*)smem_raw;
    {
        const int r0 = wm*64 + (lane >> 2);
        const int c0 = wn*32 + (lane & 3)*2;
#pragma unroll
        for (int i = 0; i < 4; i++)
#pragma unroll
            for (int j = 0; j < 4; j++){
                int rr = r0 + i*16, cc = c0 + j*8;
                Ct[rr*CP + cc]       = acc[i*4+j][0];
                Ct[rr*CP + cc + 1]   = acc[i*4+j][1];
                Ct[(rr+8)*CP + cc]   = acc[i*4+j][2];
                Ct[(rr+8)*CP + cc+1] = acc[i*4+j][3];
            }
    }
    __syncthreads();

    // ---- epilogue: one thread per row n ----
    if (tid < BM){
        const int n = nb*BM + tid;
        const float* row = Ct + tid*CP;
        const float mval = mask[b*N_ + n];

        float e[R_] = {0,0,0,0,0};
        float sq = 0.f;
        for (int d = 0; d < D_; d++){
            float qd = row[d];
            sq += qd*qd;
#pragma unroll
            for (int a = 0; a < R_; a++) e[a] += qd * we_s[d*R_ + a];
        }
        float sclq = mval / fmaxf(fabsf(mval)*sqrtf(sq), 1e-12f);

        float rr[R_] = {0,0,0,0,0};
        float sk = 0.f;
        for (int d = 0; d < D_; d++){
            float kd = row[D_ + d];
            sk += kd*kd;
#pragma unroll
            for (int a = 0; a < R_; a++) rr[a] += kd * wr_s[d*R_ + a];
        }
        float sclk = mval / fmaxf(fabsf(mval)*sqrtf(sk), 1e-12f);

        const size_t ebase = ((size_t)((b*H_ + h)*N_ + n))*R_;
        float es[R_], rs[R_], v1[R_];
#pragma unroll
        for (int a = 0; a < R_; a++){
            es[a] = e[a]*sclq;
            rs[a] = rr[a]*sclk;
            v1[a] = (es[a] + rs[a]) * lam2_s[a];
        }
        float* eo = out + ATTN_ELEMS + ebase;
        float* ro = out + ATTN_ELEMS + ESC_ELEMS + ebase;
#pragma unroll
        for (int a = 0; a < R_; a++){ eo[a] = es[a]; ro[a] = rs[a]; }

        float ev[R_];
#pragma unroll
        for (int u = 0; u < R_; u++) ev[u] = eps[ebase + u];
        float smp[R_];
#pragma unroll
        for (int s = 0; s < R_; s++){
            float am = 0.f;
#pragma unroll
            for (int a = 0; a < R_; a++) am += v1[a]*mu_s[a*R_ + s];
            smp[s] = am;
        }
#pragma unroll
        for (int a = 0; a < R_; a++)
#pragma unroll
            for (int u = 0; u < R_; u++){
                float f = v1[a]*ev[u];
#pragma unroll
                for (int c = 0; c < R_; c++)
                    smp[c] += f * S_s[(a*R_ + u)*R_ + c];
            }

        float* ob = out + ((size_t)(b*N_ + n))*C_ + h*D_;
#pragma unroll
        for (int d0 = 0; d0 < D_; d0 += 4){
            float4 o;
            float* op = (float*)&o;
#pragma unroll
            for (int dd = 0; dd < 4; dd++){
                float ao = fwb_s[d0 + dd];
#pragma unroll
                for (int a = 0; a < R_; a++) ao += smp[a]*fww_s[(d0 + dd)*R_ + a];
                op[dd] = ao;
            }
            *(float4*)(ob + d0) = o;
        }
    }
}

// ---------------------------------------------------------------------------
extern "C" void kernel_launch(void* const* d_in, const int* in_sizes, int n_in,
                              void* d_out, int out_size)
{
    const float* x         = (const float*)d_in[0];
    const float* mask      = (const float*)d_in[1];
    const float* eps       = (const float*)d_in[2];
    const float* qk_w      = (const float*)d_in[3];
    const float* we_p      = (const float*)d_in[4];
    const float* wr_p      = (const float*)d_in[5];
    const float* log_lam   = (const float*)d_in[6];
    const float* m_u       = (const float*)d_in[7];
    const float* s_tri     = (const float*)d_in[8];
    const float* log_ssqrt = (const float*)d_in[9];
    const float* fw_w      = (const float*)d_in[10];
    const float* fw_b      = (const float*)d_in[11];
    float* out = (float*)d_out;

    k_prep<<<NB_CONV + 129, 256>>>(x, qk_w, we_p, wr_p, log_lam, m_u, s_tri,
                                   log_ssqrt, out + ATTN_ELEMS + 2*ESC_ELEMS);

    cudaFuncSetAttribute(k_main, cudaFuncAttributeMaxDynamicSharedMemorySize, SMEM_DYN);
    dim3 grid(N_/BM, H_, B_);
    k_main<<<grid, 256, SMEM_DYN>>>(mask, eps, log_lam, m_u, fw_w, fw_b, out);
}

// round 14
// speedup vs baseline: 1.1439x; 1.0529x over previous
#include <cuda_runtime.h>
#include <cuda_fp16.h>
#include <math.h>
#include <stdint.h>

#define B_ 8
#define N_ 2048
#define C_ 1024
#define H_ 16
#define D_ 64
#define R_ 5
#define RM_ 10

#define ATTN_ELEMS ((size_t)B_*N_*C_)              // 16777216
#define ESC_ELEMS  ((size_t)B_*H_*N_*R_)           // 1310720

// GEMM tiling
#define BM 128
#define BN 128
#define BK 32                 // K elems per stage
#define NSTAGE (C_/BK)        // 32
#define ROWP 40               // padded smem row stride in fp16 elems (80B)
#define TERM_BYTES (128*ROWP*2)          // one 128-row tile, 10240 B
#define STAGE_BYTES (3*TERM_BYTES)       // Ahi Bhi Blo = 30720 B
#define NBUF 3
#define CP 129
#define SMEM_DYN (NBUF*STAGE_BYTES)      // 92160 (>= C tile 128*129*4 = 66048)

// combined scratch: one base pointer, uint32 element offsets
// layout: x hi | w hi | w lo   (x lo never needed — correction lives on B side)
#define XN ((uint32_t)(B_*N_*C_))        // 16777216
#define WN ((uint32_t)(2*C_*C_))         // 2097152
#define OFF_XHI 0u
#define OFF_WHI XN
#define OFF_WLO (XN + WN)

#define NB_CONV 4096

__device__ __align__(256) __half g_hl[(size_t)(XN + 2u*WN)];
__device__ float g_we[B_*H_*D_*R_];
__device__ float g_wr[B_*H_*D_*R_];
__device__ float g_S[H_*R_*R_*R_];

__constant__ int c_idx[RM_] = {0,227,454,682,909,1137,1364,1592,1819,2047};

// ---------------- PTX helpers (all baseline / portable) ----------------
__device__ __forceinline__ uint32_t smem_u32(const void* p){
    uint32_t a;
    asm("{ .reg .u64 t; cvta.to.shared.u64 t, %1; cvt.u32.u64 %0, t; }" : "=r"(a) : "l"(p));
    return a;
}
__device__ __forceinline__ void ldgsts16(uint32_t dst, const void* src){
    asm volatile("cp.async.cg.shared.global [%0], [%1], 16;" :: "r"(dst), "l"(src));
}
__device__ __forceinline__ void cp_commit(){ asm volatile("cp.async.commit_group;" ::: "memory"); }
__device__ __forceinline__ void cp_wait1(){ asm volatile("cp.async.wait_group 1;" ::: "memory"); }
__device__ __forceinline__ void cp_wait0(){ asm volatile("cp.async.wait_group 0;" ::: "memory"); }

__device__ __forceinline__ void ldm_x4(uint32_t* r, uint32_t addr){
    asm volatile("ldmatrix.sync.aligned.m8n8.x4.shared.b16 {%0,%1,%2,%3}, [%4];"
        : "=r"(r[0]),"=r"(r[1]),"=r"(r[2]),"=r"(r[3]) : "r"(addr));
}
__device__ __forceinline__ void mma_f16(float* d, const uint32_t* a, uint32_t b0, uint32_t b1){
    asm volatile("mma.sync.aligned.m16n8k16.row.col.f32.f16.f16.f32 "
        "{%0,%1,%2,%3}, {%4,%5,%6,%7}, {%8,%9}, {%0,%1,%2,%3};"
        : "+f"(d[0]),"+f"(d[1]),"+f"(d[2]),"+f"(d[3])
        : "r"(a[0]),"r"(a[1]),"r"(a[2]),"r"(a[3]), "r"(b0),"r"(b1));
}

// ---------------------------------------------------------------------------
// Fused prep kernel:
//   blocks [0, NB_CONV):            x -> fp16 hi; qk_w -> fp16 hi+lo split
//   blocks [NB_CONV, NB_CONV+128):  we/wr inducing-point projections
//   block  NB_CONV+128:             S matrices + KL scalar
// ---------------------------------------------------------------------------
__global__ void k_prep(const float* __restrict__ x, const float* __restrict__ qk_w,
                       const float* __restrict__ we_p, const float* __restrict__ wr_p,
                       const float* __restrict__ log_lam, const float* __restrict__ m_u,
                       const float* __restrict__ s_tri, const float* __restrict__ log_ssqrt,
                       float* __restrict__ kl_out)
{
    __shared__ float part[256];
    const int bid = blockIdx.x;

    if (bid < NB_CONV){
        const size_t nx4 = (size_t)XN/4;
        const size_t nw4 = (size_t)WN/4;
        const size_t tot = nx4 + nw4;
        const size_t stride = (size_t)NB_CONV*256;
        uint2* g4 = (uint2*)g_hl;
        for (size_t t = (size_t)bid*256 + threadIdx.x; t < tot; t += stride){
            if (t < nx4){
                float4 v = ((const float4*)x)[t];
                uint2 hp;
                hp.x = ((uint32_t)__half_as_ushort(__float2half_rn(v.y)) << 16)
                     | __half_as_ushort(__float2half_rn(v.x));
                hp.y = ((uint32_t)__half_as_ushort(__float2half_rn(v.w)) << 16)
                     | __half_as_ushort(__float2half_rn(v.z));
                g4[OFF_XHI/4 + t] = hp;
            } else {
                size_t w = t - nx4;
                float4 v = ((const float4*)qk_w)[w];
                __half h0 = __float2half_rn(v.x);
                __half h1 = __float2half_rn(v.y);
                __half h2 = __float2half_rn(v.z);
                __half h3 = __float2half_rn(v.w);
                __half l0 = __float2half_rn(v.x - __half2float(h0));
                __half l1 = __float2half_rn(v.y - __half2float(h1));
                __half l2 = __float2half_rn(v.z - __half2float(h2));
                __half l3 = __float2half_rn(v.w - __half2float(h3));
                uint2 hp, lp;
                hp.x = ((uint32_t)__half_as_ushort(h1) << 16) | __half_as_ushort(h0);
                hp.y = ((uint32_t)__half_as_ushort(h3) << 16) | __half_as_ushort(h2);
                lp.x = ((uint32_t)__half_as_ushort(l1) << 16) | __half_as_ushort(l0);
                lp.y = ((uint32_t)__half_as_ushort(l3) << 16) | __half_as_ushort(l2);
                g4[OFF_WHI/4 + w] = hp;
                g4[OFF_WLO/4 + w] = lp;
            }
        }
    } else if (bid < NB_CONV + 128){
        const int b2 = bid - NB_CONV;
        const int b = b2 >> 4, h = b2 & 15;
        const int d = threadIdx.x;
        if (d < D_){
            float xs[RM_];
#pragma unroll
            for (int m = 0; m < RM_; m++)
                xs[m] = x[((size_t)(b*N_ + c_idx[m]))*C_ + h*D_ + d];
#pragma unroll
            for (int a = 0; a < R_; a++){
                float se = 0.f, sr = 0.f;
#pragma unroll
                for (int m = 0; m < RM_; m++){
                    se += xs[m] * we_p[(h*RM_ + m)*R_ + a];
                    sr += xs[m] * wr_p[(h*RM_ + m)*R_ + a];
                }
                g_we[((b*H_ + h)*D_ + d)*R_ + a] = se;
                g_wr[((b*H_ + h)*D_ + d)*R_ + a] = sr;
            }
        }
    } else {
        const int t = threadIdx.x;
        for (int i = t; i < H_*R_*R_*R_; i += 256){
            int c = i % R_;
            int u = (i / R_) % R_;
            int a = (i / (R_*R_)) % R_;
            int h = i / (R_*R_*R_);
            float v = 0.f;
            if (u == c)      v = expf(log_ssqrt[(h*R_ + a)*R_ + u]);
            else if (u > c)  v = s_tri[((h*R_ + a)*R_ + u)*R_ + c];
            g_S[i] = v;
        }
        float p = 0.f;
        if (t < H_*R_){
            int h = t / R_, a = t % R_;
            float ll = log_lam[t];
            float e4 = expf(4.f*ll);
            float ss2 = 0.f;
            for (int u = 0; u < R_; u++){
                float dg = expf(log_ssqrt[(h*R_ + a)*R_ + u]);
                ss2 += dg*dg;
                for (int c = 0; c < u; c++){
                    float v = s_tri[((h*R_ + a)*R_ + u)*R_ + c];
                    ss2 += v*v;
                }
            }
            float mm = 0.f;
            for (int s = 0; s < R_; s++){
                float v = m_u[(h*R_ + a)*R_ + s];
                mm += v*v;
            }
            float lsum = 0.f;
            for (int u = 0; u < R_; u++) lsum += log_ssqrt[(h*R_ + a)*R_ + u];
            p = 0.5f*e4*(ss2 + mm) - lsum - 2.f*(float)R_*ll
                - (0.5f*(float)(R_*R_*H_)) / (float)(H_*R_);
        }
        part[t] = p;
        __syncthreads();
        if (t == 0){
            float s = 0.f;
            for (int i = 0; i < H_*R_; i++) s += part[i];
            *kl_out = s;
        }
    }
}

// ---------------------------------------------------------------------------
// Fused main kernel: 128x128x1024 fp16 B-split (2-term) mma.sync GEMM + epilogue
// NBUF=3 ring, lookahead 1, ONE barrier per stage, 2 CTAs/SM.
// A = x(hi); B terms = w(hi), w(lo). acc = ah*bh + ah*bl.
// ---------------------------------------------------------------------------
extern __shared__ char smem_raw[];

__global__ __launch_bounds__(256, 2)
void k_main(const float* __restrict__ mask,
            const float* __restrict__ eps,
            const float* __restrict__ log_lam,
            const float* __restrict__ m_u,
            const float* __restrict__ fw_w,
            const float* __restrict__ fw_b,
            float* __restrict__ out)
{
    const int nb = blockIdx.x, h = blockIdx.y, b = blockIdx.z;
    const int tid = threadIdx.x;
    const int wid = tid >> 5;
    const int lane = tid & 31;
    const uint32_t sb = smem_u32(smem_raw);

    __shared__ float we_s[D_*R_], wr_s[D_*R_], fww_s[D_*R_];
    __shared__ float S_s[R_*R_*R_], mu_s[R_*R_], lam2_s[R_], fwb_s[D_];

    {
        int base = (b*H_ + h)*D_*R_;
        for (int i = tid; i < D_*R_; i += 256){
            we_s[i] = g_we[base + i];
            wr_s[i] = g_wr[base + i];
            fww_s[i] = fw_w[i];
        }
        for (int i = tid; i < R_*R_*R_; i += 256) S_s[i] = g_S[h*R_*R_*R_ + i];
        for (int i = tid; i < R_*R_; i += 256)    mu_s[i] = m_u[h*R_*R_ + i];
        if (tid < R_)  lam2_s[tid] = expf(2.f*log_lam[h*R_ + tid]);
        if (tid < D_)  fwb_s[tid] = fw_b[tid];
    }

    const int rowA0 = b*N_ + nb*BM;

    // ---- cp.async load geometry: 6 chunks of 16B per thread per stage ----
    // tile 0 = A(x hi), tile 1 = B hi (w), tile 2 = B lo (w)
    uint32_t goff[6];
    uint32_t soff[6];
#pragma unroll
    for (int i = 0; i < 6; i++){
        int c = i*256 + tid;
        int tile = c >> 9;
        int row  = (c >> 2) & 127;
        int quad = c & 3;
        soff[i] = tile*TERM_BYTES + row*(ROWP*2) + quad*16;
        if (tile == 0)
            goff[i] = OFF_XHI + (uint32_t)(rowA0 + row)*C_ + quad*8;
        else {
            int wj = (row < 64) ? (h*64 + row) : (C_ + h*64 + (row - 64));
            goff[i] = ((tile == 1) ? OFF_WHI : OFF_WLO) + (uint32_t)wj*C_ + quad*8;
        }
    }

    auto load_stage = [&](int kt, int buf){
        uint32_t stb = sb + buf*STAGE_BYTES;
        uint32_t ke = (uint32_t)kt*BK;
#pragma unroll
        for (int i = 0; i < 6; i++)
            ldgsts16(stb + soff[i], g_hl + (size_t)(goff[i] + ke));
        cp_commit();
    };

    // ---- warp tile geometry (64x32 per warp, 2x4 grid) ----
    const int wm = wid >> 2;
    const int wn = wid & 3;
    const int arow = lane & 15, acol8 = lane >> 4;

    uint32_t aoff[4], boff[2];
#pragma unroll
    for (int i = 0; i < 4; i++)
        aoff[i] = (wm*64 + i*16 + arow)*(ROWP*2) + acol8*16;
#pragma unroll
    for (int p = 0; p < 2; p++)
        boff[p] = (wn*32 + p*16 + arow)*(ROWP*2) + acol8*16;

    float acc[16][4];
#pragma unroll
    for (int i = 0; i < 16; i++)
#pragma unroll
        for (int j = 0; j < 4; j++) acc[i][j] = 0.f;

    // ---- pipeline: NBUF=3 ring, lookahead 1, single barrier per stage ----
    load_stage(0, 0);

    int buf_next = 1;
    int buf_cur = 0;
    for (int kt = 0; kt < NSTAGE; kt++){
        if (kt + 1 < NSTAGE){
            load_stage(kt + 1, buf_next);
            cp_wait1();
        } else {
            cp_wait0();
        }
        __syncthreads();   // single barrier per stage (ring distance 2 mod 3)

        const uint32_t Ah = sb + buf_cur*STAGE_BYTES;
        const uint32_t Bh = Ah + TERM_BYTES;
        const uint32_t Bl = Ah + 2*TERM_BYTES;

        buf_cur = buf_next;
        buf_next = (buf_next + 1 == NBUF) ? 0 : buf_next + 1;

#pragma unroll
        for (int kk = 0; kk < 2; kk++){
            const uint32_t kb = kk*32;
            uint32_t ah[4][4], bh[2][4];
#pragma unroll
            for (int i = 0; i < 4; i++) ldm_x4(ah[i], Ah + aoff[i] + kb);
#pragma unroll
            for (int p = 0; p < 2; p++) ldm_x4(bh[p], Bh + boff[p] + kb);
            // hh term
#pragma unroll
            for (int i = 0; i < 4; i++)
#pragma unroll
                for (int j = 0; j < 4; j++){
                    int p = j >> 1, s = j & 1;
                    mma_f16(acc[i*4+j], ah[i], bh[p][s], bh[p][2+s]);
                }
            // hl term (B-lo correction; ah reused)
            {
                uint32_t bl[2][4];
#pragma unroll
                for (int p = 0; p < 2; p++) ldm_x4(bl[p], Bl + boff[p] + kb);
#pragma unroll
                for (int i = 0; i < 4; i++)
#pragma unroll
                    for (int j = 0; j < 4; j++){
                        int p = j >> 1, s = j & 1;
                        mma_f16(acc[i*4+j], ah[i], bl[p][s], bl[p][2+s]);
                    }
            }
        }
    }
    __syncthreads();   // all MMAs/reads done before C-tile overwrite

    // ---- write C tile to smem (reuse stage buffers) ----
    float* Ct = (float*)smem_raw;
    {
        const int r0 = wm*64 + (lane >> 2);
        const int c0 = wn*32 + (lane & 3)*2;
#pragma unroll
        for (int i = 0; i < 4; i++)
#pragma unroll
            for (int j = 0; j < 4; j++){
                int rr = r0 + i*16, cc = c0 + j*8;
                Ct[rr*CP + cc]       = acc[i*4+j][0];
                Ct[rr*CP + cc + 1]   = acc[i*4+j][1];
                Ct[(rr+8)*CP + cc]   = acc[i*4+j][2];
                Ct[(rr+8)*CP + cc+1] = acc[i*4+j][3];
            }
    }
    __syncthreads();

    // ---- epilogue: one thread per row n ----
    if (tid < BM){
        const int n = nb*BM + tid;
        const float* row = Ct + tid*CP;
        const float mval = mask[b*N_ + n];

        float e[R_] = {0,0,0,0,0};
        float sq = 0.f;
        for (int d = 0; d < D_; d++){
            float qd = row[d];
            sq += qd*qd;
#pragma unroll
            for (int a = 0; a < R_; a++) e[a] += qd * we_s[d*R_ + a];
        }
        float sclq = mval / fmaxf(fabsf(mval)*sqrtf(sq), 1e-12f);

        float rr[R_] = {0,0,0,0,0};
        float sk = 0.f;
        for (int d = 0; d < D_; d++){
            float kd = row[D_ + d];
            sk += kd*kd;
#pragma unroll
            for (int a = 0; a < R_; a++) rr[a] += kd * wr_s[d*R_ + a];
        }
        float sclk = mval / fmaxf(fabsf(mval)*sqrtf(sk), 1e-12f);

        const size_t ebase = ((size_t)((b*H_ + h)*N_ + n))*R_;
        float es[R_], rs[R_], v1[R_];
#pragma unroll
        for (int a = 0; a < R_; a++){
            es[a] = e[a]*sclq;
            rs[a] = rr[a]*sclk;
            v1[a] = (es[a] + rs[a]) * lam2_s[a];
        }
        float* eo = out + ATTN_ELEMS + ebase;
        float* ro = out + ATTN_ELEMS + ESC_ELEMS + ebase;
#pragma unroll
        for (int a = 0; a < R_; a++){ eo[a] = es[a]; ro[a] = rs[a]; }

        float ev[R_];
#pragma unroll
        for (int u = 0; u < R_; u++) ev[u] = eps[ebase + u];
        float smp[R_];
#pragma unroll
        for (int s = 0; s < R_; s++){
            float am = 0.f;
#pragma unroll
            for (int a = 0; a < R_; a++) am += v1[a]*mu_s[a*R_ + s];
            smp[s] = am;
        }
#pragma unroll
        for (int a = 0; a < R_; a++)
#pragma unroll
            for (int u = 0; u < R_; u++){
                float f = v1[a]*ev[u];
#pragma unroll
                for (int c = 0; c < R_; c++)
                    smp[c] += f * S_s[(a*R_ + u)*R_ + c];
            }

        float* ob = out + ((size_t)(b*N_ + n))*C_ + h*D_;
#pragma unroll
        for (int d0 = 0; d0 < D_; d0 += 4){
            float4 o;
            float* op = (float*)&o;
#pragma unroll
            for (int dd = 0; dd < 4; dd++){
                float ao = fwb_s[d0 + dd];
#pragma unroll
                for (int a = 0; a < R_; a++) ao += smp[a]*fww_s[(d0 + dd)*R_ + a];
                op[dd] = ao;
            }
            *(float4*)(ob + d0) = o;
        }
    }
}

// ---------------------------------------------------------------------------
extern "C" void kernel_launch(void* const* d_in, const int* in_sizes, int n_in,
                              void* d_out, int out_size)
{
    const float* x         = (const float*)d_in[0];
    const float* mask      = (const float*)d_in[1];
    const float* eps       = (const float*)d_in[2];
    const float* qk_w      = (const float*)d_in[3];
    const float* we_p      = (const float*)d_in[4];
    const float* wr_p      = (const float*)d_in[5];
    const float* log_lam   = (const float*)d_in[6];
    const float* m_u       = (const float*)d_in[7];
    const float* s_tri     = (const float*)d_in[8];
    const float* log_ssqrt = (const float*)d_in[9];
    const float* fw_w      = (const float*)d_in[10];
    const float* fw_b      = (const float*)d_in[11];
    float* out = (float*)d_out;

    k_prep<<<NB_CONV + 129, 256>>>(x, qk_w, we_p, wr_p, log_lam, m_u, s_tri,
                                   log_ssqrt, out + ATTN_ELEMS + 2*ESC_ELEMS);

    cudaFuncSetAttribute(k_main, cudaFuncAttributeMaxDynamicSharedMemorySize, SMEM_DYN);
    dim3 grid(N_/BM, H_, B_);
    k_main<<<grid, 256, SMEM_DYN>>>(mask, eps, log_lam, m_u, fw_w, fw_b, out);
}

// round 15
// speedup vs baseline: 1.7707x; 1.5479x over previous
#include <cuda_runtime.h>
#include <cuda_fp16.h>
#include <math.h>
#include <stdint.h>

#define B_ 8
#define N_ 2048
#define C_ 1024
#define H_ 16
#define D_ 64
#define R_ 5
#define RM_ 10

#define ATTN_ELEMS ((size_t)B_*N_*C_)              // 16777216
#define ESC_ELEMS  ((size_t)B_*H_*N_*R_)           // 1310720

// GEMM tiling
#define BM 128
#define BN 128
#define BK 32                 // K elems per stage
#define NSTAGE (C_/BK)        // 32
#define ROWP 40               // padded smem row stride in fp16 elems (80B)
#define TERM_BYTES (128*ROWP*2)          // one 128-row tile, 10240 B
#define STAGE_BYTES (2*TERM_BYTES)       // Ahi Bhi = 20480 B
#define NBUF 3
#define CP 129
#define SMEM_DYN (BM*CP*4)               // 66048 (>= NBUF*STAGE_BYTES = 61440)

// fp16 scratch: x hi | w hi
#define XN ((uint32_t)(B_*N_*C_))        // 16777216
#define WN ((uint32_t)(2*C_*C_))         // 2097152
#define OFF_XHI 0u
#define OFF_WHI XN

#define NB_CONV 4096

__device__ __align__(256) __half g_hl[(size_t)(XN + WN)];
__device__ float g_we[B_*H_*D_*R_];
__device__ float g_wr[B_*H_*D_*R_];
__device__ float g_S[H_*R_*R_*R_];

__constant__ int c_idx[RM_] = {0,227,454,682,909,1137,1364,1592,1819,2047};

// ---------------- PTX helpers (all baseline / portable) ----------------
__device__ __forceinline__ uint32_t smem_u32(const void* p){
    uint32_t a;
    asm("{ .reg .u64 t; cvta.to.shared.u64 t, %1; cvt.u32.u64 %0, t; }" : "=r"(a) : "l"(p));
    return a;
}
__device__ __forceinline__ void ldgsts16(uint32_t dst, const void* src){
    asm volatile("cp.async.cg.shared.global [%0], [%1], 16;" :: "r"(dst), "l"(src));
}
__device__ __forceinline__ void cp_commit(){ asm volatile("cp.async.commit_group;" ::: "memory"); }
__device__ __forceinline__ void cp_wait1(){ asm volatile("cp.async.wait_group 1;" ::: "memory"); }
__device__ __forceinline__ void cp_wait0(){ asm volatile("cp.async.wait_group 0;" ::: "memory"); }

__device__ __forceinline__ void ldm_x4(uint32_t* r, uint32_t addr){
    asm volatile("ldmatrix.sync.aligned.m8n8.x4.shared.b16 {%0,%1,%2,%3}, [%4];"
        : "=r"(r[0]),"=r"(r[1]),"=r"(r[2]),"=r"(r[3]) : "r"(addr));
}
__device__ __forceinline__ void mma_f16(float* d, const uint32_t* a, uint32_t b0, uint32_t b1){
    asm volatile("mma.sync.aligned.m16n8k16.row.col.f32.f16.f16.f32 "
        "{%0,%1,%2,%3}, {%4,%5,%6,%7}, {%8,%9}, {%0,%1,%2,%3};"
        : "+f"(d[0]),"+f"(d[1]),"+f"(d[2]),"+f"(d[3])
        : "r"(a[0]),"r"(a[1]),"r"(a[2]),"r"(a[3]), "r"(b0),"r"(b1));
}

// ---------------------------------------------------------------------------
// Fused prep kernel:
//   blocks [0, NB_CONV):            x, qk_w -> fp16
//   blocks [NB_CONV, NB_CONV+128):  we/wr inducing-point projections
//   block  NB_CONV+128:             S matrices + KL scalar
// ---------------------------------------------------------------------------
__global__ void k_prep(const float* __restrict__ x, const float* __restrict__ qk_w,
                       const float* __restrict__ we_p, const float* __restrict__ wr_p,
                       const float* __restrict__ log_lam, const float* __restrict__ m_u,
                       const float* __restrict__ s_tri, const float* __restrict__ log_ssqrt,
                       float* __restrict__ kl_out)
{
    __shared__ float part[256];
    const int bid = blockIdx.x;

    if (bid < NB_CONV){
        const size_t nx4 = (size_t)XN/4;
        const size_t nw4 = (size_t)WN/4;
        const size_t tot = nx4 + nw4;
        const size_t stride = (size_t)NB_CONV*256;
        uint2* g4 = (uint2*)g_hl;
        for (size_t t = (size_t)bid*256 + threadIdx.x; t < tot; t += stride){
            float4 v = (t < nx4) ? ((const float4*)x)[t] : ((const float4*)qk_w)[t - nx4];
            uint2 hp;
            hp.x = ((uint32_t)__half_as_ushort(__float2half_rn(v.y)) << 16)
                 | __half_as_ushort(__float2half_rn(v.x));
            hp.y = ((uint32_t)__half_as_ushort(__float2half_rn(v.w)) << 16)
                 | __half_as_ushort(__float2half_rn(v.z));
            g4[t] = hp;   // contiguous: x hi then w hi
        }
    } else if (bid < NB_CONV + 128){
        const int b2 = bid - NB_CONV;
        const int b = b2 >> 4, h = b2 & 15;
        const int d = threadIdx.x;
        if (d < D_){
            float xs[RM_];
#pragma unroll
            for (int m = 0; m < RM_; m++)
                xs[m] = x[((size_t)(b*N_ + c_idx[m]))*C_ + h*D_ + d];
#pragma unroll
            for (int a = 0; a < R_; a++){
                float se = 0.f, sr = 0.f;
#pragma unroll
                for (int m = 0; m < RM_; m++){
                    se += xs[m] * we_p[(h*RM_ + m)*R_ + a];
                    sr += xs[m] * wr_p[(h*RM_ + m)*R_ + a];
                }
                g_we[((b*H_ + h)*D_ + d)*R_ + a] = se;
                g_wr[((b*H_ + h)*D_ + d)*R_ + a] = sr;
            }
        }
    } else {
        const int t = threadIdx.x;
        for (int i = t; i < H_*R_*R_*R_; i += 256){
            int c = i % R_;
            int u = (i / R_) % R_;
            int a = (i / (R_*R_)) % R_;
            int h = i / (R_*R_*R_);
            float v = 0.f;
            if (u == c)      v = expf(log_ssqrt[(h*R_ + a)*R_ + u]);
            else if (u > c)  v = s_tri[((h*R_ + a)*R_ + u)*R_ + c];
            g_S[i] = v;
        }
        float p = 0.f;
        if (t < H_*R_){
            int h = t / R_, a = t % R_;
            float ll = log_lam[t];
            float e4 = expf(4.f*ll);
            float ss2 = 0.f;
            for (int u = 0; u < R_; u++){
                float dg = expf(log_ssqrt[(h*R_ + a)*R_ + u]);
                ss2 += dg*dg;
                for (int c = 0; c < u; c++){
                    float v = s_tri[((h*R_ + a)*R_ + u)*R_ + c];
                    ss2 += v*v;
                }
            }
            float mm = 0.f;
            for (int s = 0; s < R_; s++){
                float v = m_u[(h*R_ + a)*R_ + s];
                mm += v*v;
            }
            float lsum = 0.f;
            for (int u = 0; u < R_; u++) lsum += log_ssqrt[(h*R_ + a)*R_ + u];
            p = 0.5f*e4*(ss2 + mm) - lsum - 2.f*(float)R_*ll
                - (0.5f*(float)(R_*R_*H_)) / (float)(H_*R_);
        }
        part[t] = p;
        __syncthreads();
        if (t == 0){
            float s = 0.f;
            for (int i = 0; i < H_*R_; i++) s += part[i];
            *kl_out = s;
        }
    }
}

// ---------------------------------------------------------------------------
// Fused main kernel: 128x128x1024 pure-fp16 mma.sync GEMM + epilogue
// NBUF=3 ring, lookahead 1, ONE barrier per stage, 2 CTAs/SM.
// ---------------------------------------------------------------------------
extern __shared__ char smem_raw[];

__global__ __launch_bounds__(256, 2)
void k_main(const float* __restrict__ mask,
            const float* __restrict__ eps,
            const float* __restrict__ log_lam,
            const float* __restrict__ m_u,
            const float* __restrict__ fw_w,
            const float* __restrict__ fw_b,
            float* __restrict__ out)
{
    const int nb = blockIdx.x, h = blockIdx.y, b = blockIdx.z;
    const int tid = threadIdx.x;
    const int wid = tid >> 5;
    const int lane = tid & 31;
    const uint32_t sb = smem_u32(smem_raw);

    __shared__ float we_s[D_*R_], wr_s[D_*R_], fww_s[D_*R_];
    __shared__ float S_s[R_*R_*R_], mu_s[R_*R_], lam2_s[R_], fwb_s[D_];

    {
        int base = (b*H_ + h)*D_*R_;
        for (int i = tid; i < D_*R_; i += 256){
            we_s[i] = g_we[base + i];
            wr_s[i] = g_wr[base + i];
            fww_s[i] = fw_w[i];
        }
        for (int i = tid; i < R_*R_*R_; i += 256) S_s[i] = g_S[h*R_*R_*R_ + i];
        for (int i = tid; i < R_*R_; i += 256)    mu_s[i] = m_u[h*R_*R_ + i];
        if (tid < R_)  lam2_s[tid] = expf(2.f*log_lam[h*R_ + tid]);
        if (tid < D_)  fwb_s[tid] = fw_b[tid];
    }

    const int rowA0 = b*N_ + nb*BM;

    // ---- cp.async load geometry: 4 chunks of 16B per thread per stage ----
    // tile 0 = A(x hi), tile 1 = B(w hi)
    uint32_t goff[4];
    uint32_t soff[4];
#pragma unroll
    for (int i = 0; i < 4; i++){
        int c = i*256 + tid;
        int tile = c >> 9;
        int row  = (c >> 2) & 127;
        int quad = c & 3;
        soff[i] = tile*TERM_BYTES + row*(ROWP*2) + quad*16;
        if (tile == 0)
            goff[i] = OFF_XHI + (uint32_t)(rowA0 + row)*C_ + quad*8;
        else {
            int wj = (row < 64) ? (h*64 + row) : (C_ + h*64 + (row - 64));
            goff[i] = OFF_WHI + (uint32_t)wj*C_ + quad*8;
        }
    }

    auto load_stage = [&](int kt, int buf){
        uint32_t stb = sb + buf*STAGE_BYTES;
        uint32_t ke = (uint32_t)kt*BK;
#pragma unroll
        for (int i = 0; i < 4; i++)
            ldgsts16(stb + soff[i], g_hl + (size_t)(goff[i] + ke));
        cp_commit();
    };

    // ---- warp tile geometry (64x32 per warp, 2x4 grid) ----
    const int wm = wid >> 2;
    const int wn = wid & 3;
    const int arow = lane & 15, acol8 = lane >> 4;

    uint32_t aoff[4], boff[2];
#pragma unroll
    for (int i = 0; i < 4; i++)
        aoff[i] = (wm*64 + i*16 + arow)*(ROWP*2) + acol8*16;
#pragma unroll
    for (int p = 0; p < 2; p++)
        boff[p] = (wn*32 + p*16 + arow)*(ROWP*2) + acol8*16;

    float acc[16][4];
#pragma unroll
    for (int i = 0; i < 16; i++)
#pragma unroll
        for (int j = 0; j < 4; j++) acc[i][j] = 0.f;

    // ---- pipeline: NBUF=3 ring, lookahead 1, single barrier per stage ----
    load_stage(0, 0);

    int buf_next = 1;
    int buf_cur = 0;
    for (int kt = 0; kt < NSTAGE; kt++){
        if (kt + 1 < NSTAGE){
            load_stage(kt + 1, buf_next);
            cp_wait1();
        } else {
            cp_wait0();
        }
        __syncthreads();   // single barrier per stage (ring distance 2 mod 3)

        const uint32_t Ah = sb + buf_cur*STAGE_BYTES;
        const uint32_t Bh = Ah + TERM_BYTES;

        buf_cur = buf_next;
        buf_next = (buf_next + 1 == NBUF) ? 0 : buf_next + 1;

#pragma unroll
        for (int kk = 0; kk < 2; kk++){
            const uint32_t kb = kk*32;
            uint32_t ah[4][4], bh[2][4];
#pragma unroll
            for (int i = 0; i < 4; i++) ldm_x4(ah[i], Ah + aoff[i] + kb);
#pragma unroll
            for (int p = 0; p < 2; p++) ldm_x4(bh[p], Bh + boff[p] + kb);
#pragma unroll
            for (int i = 0; i < 4; i++)
#pragma unroll
                for (int j = 0; j < 4; j++){
                    int p = j >> 1, s = j & 1;
                    mma_f16(acc[i*4+j], ah[i], bh[p][s], bh[p][2+s]);
                }
        }
    }
    __syncthreads();   // all MMAs/reads done before C-tile overwrite

    // ---- write C tile to smem (reuse stage buffers) ----
    float* Ct = (float*)smem_raw;
    {
        const int r0 = wm*64 + (lane >> 2);
        const int c0 = wn*32 + (lane & 3)*2;
#pragma unroll
        for (int i = 0; i < 4; i++)
#pragma unroll
            for (int j = 0; j < 4; j++){
                int rr = r0 + i*16, cc = c0 + j*8;
                Ct[rr*CP + cc]       = acc[i*4+j][0];
                Ct[rr*CP + cc + 1]   = acc[i*4+j][1];
                Ct[(rr+8)*CP + cc]   = acc[i*4+j][2];
                Ct[(rr+8)*CP + cc+1] = acc[i*4+j][3];
            }
    }
    __syncthreads();

    // ---- epilogue: one thread per row n ----
    if (tid < BM){
        const int n = nb*BM + tid;
        const float* row = Ct + tid*CP;
        const float mval = mask[b*N_ + n];

        float e[R_] = {0,0,0,0,0};
        float sq = 0.f;
        for (int d = 0; d < D_; d++){
            float qd = row[d];
            sq += qd*qd;
#pragma unroll
            for (int a = 0; a < R_; a++) e[a] += qd * we_s[d*R_ + a];
        }
        float sclq = mval / fmaxf(fabsf(mval)*sqrtf(sq), 1e-12f);

        float rr[R_] = {0,0,0,0,0};
        float sk = 0.f;
        for (int d = 0; d < D_; d++){
            float kd = row[D_ + d];
            sk += kd*kd;
#pragma unroll
            for (int a = 0; a < R_; a++) rr[a] += kd * wr_s[d*R_ + a];
        }
        float sclk = mval / fmaxf(fabsf(mval)*sqrtf(sk), 1e-12f);

        const size_t ebase = ((size_t)((b*H_ + h)*N_ + n))*R_;
        float es[R_], rs[R_], v1[R_];
#pragma unroll
        for (int a = 0; a < R_; a++){
            es[a] = e[a]*sclq;
            rs[a] = rr[a]*sclk;
            v1[a] = (es[a] + rs[a]) * lam2_s[a];
        }
        float* eo = out + ATTN_ELEMS + ebase;
        float* ro = out + ATTN_ELEMS + ESC_ELEMS + ebase;
#pragma unroll
        for (int a = 0; a < R_; a++){ eo[a] = es[a]; ro[a] = rs[a]; }

        float ev[R_];
#pragma unroll
        for (int u = 0; u < R_; u++) ev[u] = eps[ebase + u];
        float smp[R_];
#pragma unroll
        for (int s = 0; s < R_; s++){
            float am = 0.f;
#pragma unroll
            for (int a = 0; a < R_; a++) am += v1[a]*mu_s[a*R_ + s];
            smp[s] = am;
        }
#pragma unroll
        for (int a = 0; a < R_; a++)
#pragma unroll
            for (int u = 0; u < R_; u++){
                float f = v1[a]*ev[u];
#pragma unroll
                for (int c = 0; c < R_; c++)
                    smp[c] += f * S_s[(a*R_ + u)*R_ + c];
            }

        float* ob = out + ((size_t)(b*N_ + n))*C_ + h*D_;
#pragma unroll
        for (int d0 = 0; d0 < D_; d0 += 4){
            float4 o;
            float* op = (float*)&o;
#pragma unroll
            for (int dd = 0; dd < 4; dd++){
                float ao = fwb_s[d0 + dd];
#pragma unroll
                for (int a = 0; a < R_; a++) ao += smp[a]*fww_s[(d0 + dd)*R_ + a];
                op[dd] = ao;
            }
            *(float4*)(ob + d0) = o;
        }
    }
}

// ---------------------------------------------------------------------------
extern "C" void kernel_launch(void* const* d_in, const int* in_sizes, int n_in,
                              void* d_out, int out_size)
{
    const float* x         = (const float*)d_in[0];
    const float* mask      = (const float*)d_in[1];
    const float* eps       = (const float*)d_in[2];
    const float* qk_w      = (const float*)d_in[3];
    const float* we_p      = (const float*)d_in[4];
    const float* wr_p      = (const float*)d_in[5];
    const float* log_lam   = (const float*)d_in[6];
    const float* m_u       = (const float*)d_in[7];
    const float* s_tri     = (const float*)d_in[8];
    const float* log_ssqrt = (const float*)d_in[9];
    const float* fw_w      = (const float*)d_in[10];
    const float* fw_b      = (const float*)d_in[11];
    float* out = (float*)d_out;

    k_prep<<<NB_CONV + 129, 256>>>(x, qk_w, we_p, wr_p, log_lam, m_u, s_tri,
                                   log_ssqrt, out + ATTN_ELEMS + 2*ESC_ELEMS);

    cudaFuncSetAttribute(k_main, cudaFuncAttributeMaxDynamicSharedMemorySize, SMEM_DYN);
    dim3 grid(N_/BM, H_, B_);
    k_main<<<grid, 256, SMEM_DYN>>>(mask, eps, log_lam, m_u, fw_w, fw_b, out);
}